// round 8
// baseline (speedup 1.0000x reference)
#include <cuda_runtime.h>

#define BB 64
#define TT 1024
#define NN 48
#define PF 3   // 1023 steps = 341 * 3 exactly -> no tail guard, branch-free body
#define NBLK (2 * BB)   // 64 chain blocks + 64 score blocks: one block per SM

// Scratch (no cudaMalloc allowed)
__device__ float g_lognorm[BB];
__device__ float g_score[BB];
__device__ int   g_count = 0;   // combine ticket; reset by combiner each call

__global__ __launch_bounds__(96) void crf_main(
    const float* __restrict__ y_true,
    const float* __restrict__ y_pred,
    const int*   __restrict__ spk,
    const float* __restrict__ tr0,
    const float* __restrict__ tr1,
    const float* __restrict__ tr2,
    float* __restrict__ out)
{
    // Chain: Esh (3 x 48 x 48, row stride 50, conflict-free) + vsh[2][48].
    // Scores overlay the same buffer (l1 double buffer + reduction scratch).
    __shared__ __align__(16) float sbuf[3 * 2400 + 192];
    __shared__ int s_last;
    const int tid = threadIdx.x;
    const int p = tid & 1;        // i-half: 0 -> rows 0..23, 1 -> rows 24..47
    const int j = tid >> 1;       // output column 0..47

    if (blockIdx.x < BB) {
        // ================= Forward recursion: one block per batch =================
        const int b = blockIdx.x;
        float* Esh = sbuf;              // exp(TRANS), k stride 2400, row stride 50
        float* vsh = sbuf + 7200;       // [buf][48] double-buffered combined state

        for (int idx = tid; idx < 3 * 48 * 48; idx += 96) {
            int k  = idx / 2304;
            int rc = idx - k * 2304;
            int r  = rc / 48;
            int cc = rc - r * 48;
            const float* Tk = (k == 0) ? tr0 : (k == 1) ? tr1 : tr2;
            Esh[k * 2400 + r * 50 + cc] = __expf(Tk[rc]);
        }

        const float* ypb = y_pred + b * TT * NN;
        const int*   spb = spk + b * (TT - 1);

        if (tid < 48) vsh[tid] = __expf(ypb[tid]);   // v_0 = exp(state_0)

        // Register prefetch ring for emissions + transition selectors.
        float ebuf[PF];
        int   kbuf[PF];
        #pragma unroll
        for (int u = 0; u < PF; u++) {
            ebuf[u] = ypb[(1 + u) * NN + j];
            kbuf[u] = spb[u];
        }
        __syncthreads();

        float m = 0.f;
        int cur = 0;
        int t = 1;
        for (int blk = 0; blk < (TT - 1) / PF; blk++) {   // 341 iterations, no tail
            #pragma unroll
            for (int u = 0; u < PF; u++) {
                const int   kk   = kbuf[u];
                const float emit = ebuf[u];
                // Prefetch PF steps ahead (branch-free clamp).
                int tpc  = min(t + PF, TT - 1);
                int sidx = min(t + PF - 1, TT - 2);
                ebuf[u] = ypb[tpc * NN + j];
                kbuf[u] = spb[sidx];

                const float* vc = vsh + cur * 48;

                // Renorm factor: broadcast scalar + MUFU, parallel with the dot.
                float v00 = vc[0];
                float pe  = __expf(emit);
                float rp  = __fdividef(pe, v00);

                // Pointer-select transition matrix: no branch.
                const float* Ekj = Esh + kk * 2400 + (24 * p) * 50 + j;

                // This half's 24-term dot (broadcast float4 state reads).
                float a0 = 0.f, a1 = 0.f, a2 = 0.f, a3 = 0.f;
                #pragma unroll
                for (int q = 0; q < 6; q++) {
                    float4 s4 = *(const float4*)(vc + 24 * p + 4 * q);
                    a0 += s4.x * Ekj[(4 * q    ) * 50];
                    a1 += s4.y * Ekj[(4 * q + 1) * 50];
                    a2 += s4.z * Ekj[(4 * q + 2) * 50];
                    a3 += s4.w * Ekj[(4 * q + 3) * 50];
                }
                float dot = (a0 + a1) + (a2 + a3);
                dot += __shfl_xor_sync(0xffffffffu, dot, 1);  // combine i-halves

                if (p == 0) vsh[(cur ^ 1) * 48 + j] = dot * rp;
                if (tid == 0) m += __logf(v00);
                __syncthreads();
                cur ^= 1;
                t++;
            }
        }
        if (tid == 0) {
            const float* vc = vsh + cur * 48;
            float ssum = 0.f;
            for (int q = 0; q < 48; q++) ssum += vc[q];  // fixed order
            g_lognorm[b] = m + __logf(ssum);
        }
    } else {
        // ================= Score reduction: one block per batch =================
        const int b = blockIdx.x - BB;

        float* l1sh = sbuf;        // [2][48] double buffer
        float* red  = sbuf + 96;   // 96-wide reduction scratch

        // Per-thread register copies of raw TRANS: column j, rows 24p..24p+23.
        float T0[24], T1[24], T2[24];
        #pragma unroll
        for (int i = 0; i < 24; i++) {
            int rc = (24 * p + i) * NN + j;
            T0[i] = tr0[rc];
            T1[i] = tr1[rc];
            T2[i] = tr2[rc];
        }

        const float* ytb = y_true + b * TT * NN;
        const float* ypb = y_pred + b * TT * NN;
        const int*   spb = spk + b * (TT - 1);

        float pacc = 0.f, tacc = 0.f;

        // Software-pipelined loads (one t ahead).
        float l1 = ytb[j];
        float l2 = ytb[NN + j];
        float yp = ypb[j];
        int   kk = spb[0];

        for (int t2 = 0; t2 < TT - 1; t2++) {
            if (p == 0) l1sh[(t2 & 1) * 48 + j] = l1;

            int tn = min(t2 + 1, TT - 2);
            float l1n = ytb[tn * NN + j];
            float l2n = ytb[(tn + 1) * NN + j];
            float ypn = ypb[tn * NN + j];
            int   kkn = spb[tn];

            __syncthreads();   // single barrier per t (double buffer covers WAR)
            const float* l1s = l1sh + (t2 & 1) * 48 + 24 * p;
            float u0 = 0.f, u1 = 0.f;
            if (kk == 0) {
                #pragma unroll
                for (int i = 0; i < 24; i += 2) {
                    u0 += l1s[i]     * T0[i];
                    u1 += l1s[i + 1] * T0[i + 1];
                }
            } else if (kk == 1) {
                #pragma unroll
                for (int i = 0; i < 24; i += 2) {
                    u0 += l1s[i]     * T1[i];
                    u1 += l1s[i + 1] * T1[i + 1];
                }
            } else {
                #pragma unroll
                for (int i = 0; i < 24; i += 2) {
                    u0 += l1s[i]     * T2[i];
                    u1 += l1s[i + 1] * T2[i + 1];
                }
            }
            tacc += (u0 + u1) * l2;
            if (p == 0) pacc += yp * l1;

            l1 = l1n; l2 = l2n; yp = ypn; kk = kkn;
        }
        if (p == 0) {   // point-score term for t = T-1
            pacc += ypb[(TT - 1) * NN + j] * ytb[(TT - 1) * NN + j];
        }
        red[tid] = pacc + tacc;
        __syncthreads();
        if (tid == 0) {
            float ssum = 0.f;
            for (int q = 0; q < 96; q++) ssum += red[q];  // fixed order -> deterministic
            g_score[b] = ssum;
        }
    }

    // ================= Fused combine: last block to finish does it =================
    __threadfence();                       // publish this block's results
    if (tid == 0) {
        int c = atomicAdd(&g_count, 1);
        s_last = (c == NBLK - 1);
    }
    __syncthreads();
    if (s_last) {
        __threadfence();                   // all other blocks' writes now visible
        if (tid < BB) out[tid] = g_lognorm[tid] - g_score[tid];
        if (tid == 0) g_count = 0;         // reset for next graph replay
    }
}

extern "C" void kernel_launch(void* const* d_in, const int* in_sizes, int n_in,
                              void* d_out, int out_size)
{
    const float* y_true = (const float*)d_in[0];
    const float* y_pred = (const float*)d_in[1];
    const int*   spkseq = (const int*)d_in[2];
    const float* tr0    = (const float*)d_in[3];
    const float* tr1    = (const float*)d_in[4];
    const float* tr2    = (const float*)d_in[5];

    crf_main<<<NBLK, 96>>>(y_true, y_pred, spkseq, tr0, tr1, tr2, (float*)d_out);
}

// round 9
// speedup vs baseline: 1.1738x; 1.1738x over previous
#include <cuda_runtime.h>

#define BB 64
#define TT 1024
#define NN 48
#define CH 2
#define PF 3   // 1023 steps = 341 * 3 exactly -> no tail guard, branch-free body
#define NBLK (BB + BB * CH)   // 64 chains + 128 scores = 192 blocks

// Scratch (no cudaMalloc allowed)
__device__ float g_lognorm[BB];
__device__ float g_part[BB][CH];
__device__ int   g_count = 0;   // combine ticket; reset by combiner each call

__global__ __launch_bounds__(96) void crf_main(
    const float* __restrict__ y_true,
    const float* __restrict__ y_pred,
    const int*   __restrict__ spk,
    const float* __restrict__ tr0,
    const float* __restrict__ tr1,
    const float* __restrict__ tr2,
    float* __restrict__ out)
{
    // Chain: Esh (3 x 48 x 48, row stride 50, conflict-free) + vsh[2][2][48].
    // Scores overlay the same buffer.
    __shared__ __align__(16) float sbuf[3 * 2400 + 192];
    __shared__ int s_last;
    const int tid = threadIdx.x;
    const int p = tid & 1;        // i-half: 0 -> rows 0..23, 1 -> rows 24..47
    const int j = tid >> 1;       // output column 0..47

    if (blockIdx.x < BB) {
        // ================= Forward recursion: one block per batch =================
        const int b = blockIdx.x;
        float* Esh = sbuf;              // exp(TRANS), k stride 2400, row stride 50
        float* vsh = sbuf + 7200;       // [buf][part][48]

        for (int idx = tid; idx < 3 * 48 * 48; idx += 96) {
            int k  = idx / 2304;
            int rc = idx - k * 2304;
            int r  = rc / 48;
            int cc = rc - r * 48;
            const float* Tk = (k == 0) ? tr0 : (k == 1) ? tr1 : tr2;
            Esh[k * 2400 + r * 50 + cc] = __expf(Tk[rc]);
        }

        const float* ypb = y_pred + b * TT * NN;
        const int*   spb = spk + b * (TT - 1);

        // v_0 = exp(state_0) in A-partials, zeros in B-partials.
        if (tid < 48) {
            vsh[tid]      = __expf(ypb[tid]);
            vsh[48 + tid] = 0.f;
        }

        // Register prefetch ring for emissions + transition selectors.
        float ebuf[PF];
        int   kbuf[PF];
        #pragma unroll
        for (int u = 0; u < PF; u++) {
            ebuf[u] = ypb[(1 + u) * NN + j];
            kbuf[u] = spb[u];
        }
        __syncthreads();

        float m = 0.f;
        int cur = 0;
        int t = 1;
        for (int blk = 0; blk < (TT - 1) / PF; blk++) {   // 341 iterations, no tail
            #pragma unroll
            for (int u = 0; u < PF; u++) {
                const int   kk   = kbuf[u];
                const float emit = ebuf[u];
                // Prefetch PF steps ahead (branch-free clamp).
                int tpc  = min(t + PF, TT - 1);
                int sidx = min(t + PF - 1, TT - 2);
                ebuf[u] = ypb[tpc * NN + j];
                kbuf[u] = spb[sidx];

                const float* A  = vsh + cur * 96;
                const float* Bv = A + 48;

                // Renorm factor: broadcast scalars + MUFU, parallel with the dot.
                float v00 = A[0] + Bv[0];
                float pe  = __expf(emit);
                float rp  = __fdividef(pe, v00);

                // Pointer-select transition matrix: no branch.
                const float* Ekj = Esh + kk * 2400 + (24 * p) * 50 + j;

                // Combined state slice + 24-term dot, 6 independent accumulators
                // (4-deep each) -> shorter serial chain than 4x6.
                float a0, a1, a2, a3, a4, a5;
                {
                    float4 x0 = *(const float4*)(A  + 24 * p +  0);
                    float4 y0 = *(const float4*)(Bv + 24 * p +  0);
                    a0 = (x0.x + y0.x) * Ekj[0 * 50];
                    a0 += (x0.y + y0.y) * Ekj[1 * 50];
                    a0 += (x0.z + y0.z) * Ekj[2 * 50];
                    a0 += (x0.w + y0.w) * Ekj[3 * 50];
                    float4 x1 = *(const float4*)(A  + 24 * p +  4);
                    float4 y1 = *(const float4*)(Bv + 24 * p +  4);
                    a1 = (x1.x + y1.x) * Ekj[4 * 50];
                    a1 += (x1.y + y1.y) * Ekj[5 * 50];
                    a1 += (x1.z + y1.z) * Ekj[6 * 50];
                    a1 += (x1.w + y1.w) * Ekj[7 * 50];
                    float4 x2 = *(const float4*)(A  + 24 * p +  8);
                    float4 y2 = *(const float4*)(Bv + 24 * p +  8);
                    a2 = (x2.x + y2.x) * Ekj[8 * 50];
                    a2 += (x2.y + y2.y) * Ekj[9 * 50];
                    a2 += (x2.z + y2.z) * Ekj[10 * 50];
                    a2 += (x2.w + y2.w) * Ekj[11 * 50];
                    float4 x3 = *(const float4*)(A  + 24 * p + 12);
                    float4 y3 = *(const float4*)(Bv + 24 * p + 12);
                    a3 = (x3.x + y3.x) * Ekj[12 * 50];
                    a3 += (x3.y + y3.y) * Ekj[13 * 50];
                    a3 += (x3.z + y3.z) * Ekj[14 * 50];
                    a3 += (x3.w + y3.w) * Ekj[15 * 50];
                    float4 x4 = *(const float4*)(A  + 24 * p + 16);
                    float4 y4 = *(const float4*)(Bv + 24 * p + 16);
                    a4 = (x4.x + y4.x) * Ekj[16 * 50];
                    a4 += (x4.y + y4.y) * Ekj[17 * 50];
                    a4 += (x4.z + y4.z) * Ekj[18 * 50];
                    a4 += (x4.w + y4.w) * Ekj[19 * 50];
                    float4 x5 = *(const float4*)(A  + 24 * p + 20);
                    float4 y5 = *(const float4*)(Bv + 24 * p + 20);
                    a5 = (x5.x + y5.x) * Ekj[20 * 50];
                    a5 += (x5.y + y5.y) * Ekj[21 * 50];
                    a5 += (x5.z + y5.z) * Ekj[22 * 50];
                    a5 += (x5.w + y5.w) * Ekj[23 * 50];
                }
                float dot = ((a0 + a1) + (a2 + a3)) + (a4 + a5);

                // Store this half's partial of the next state (no shfl, no combine).
                vsh[(cur ^ 1) * 96 + p * 48 + j] = dot * rp;
                if (tid == 0) m += __logf(v00);
                __syncthreads();
                cur ^= 1;
                t++;
            }
        }
        if (tid == 0) {
            const float* A = vsh + cur * 96;
            float ssum = 0.f;
            for (int q = 0; q < 48; q++) ssum += A[q] + A[48 + q];  // fixed order
            g_lognorm[b] = m + __logf(ssum);
        }
    } else {
        // ================= Score reductions: (b, chunk) blocks =================
        int idx = blockIdx.x - BB;
        int b   = idx / CH;
        int c   = idx - b * CH;

        float* l1sh = sbuf;        // [2][48] double buffer
        float* red  = sbuf + 96;   // 96-wide reduction scratch

        // Per-thread register copies of raw TRANS: column j, rows 24p..24p+23.
        float T0[24], T1[24], T2[24];
        #pragma unroll
        for (int i = 0; i < 24; i++) {
            int rc = (24 * p + i) * NN + j;
            T0[i] = tr0[rc];
            T1[i] = tr1[rc];
            T2[i] = tr2[rc];
        }

        const float* ytb = y_true + b * TT * NN;
        const float* ypb = y_pred + b * TT * NN;
        const int*   spb = spk + b * (TT - 1);

        const int LEN = (TT - 1 + CH - 1) / CH;   // 512
        int tA  = c * LEN;
        int tBn = tA + LEN; if (tBn > TT - 1) tBn = TT - 1;

        float pacc = 0.f, tacc = 0.f;

        // Software-pipelined loads (one t ahead).
        float l1 = ytb[tA * NN + j];
        float l2 = ytb[(tA + 1) * NN + j];
        float yp = ypb[tA * NN + j];
        int   kk = spb[tA];

        for (int t2 = tA; t2 < tBn; t2++) {
            if (p == 0) l1sh[(t2 & 1) * 48 + j] = l1;

            int tn = min(t2 + 1, tBn - 1);
            float l1n = ytb[tn * NN + j];
            float l2n = ytb[(tn + 1) * NN + j];
            float ypn = ypb[tn * NN + j];
            int   kkn = spb[tn];

            __syncthreads();   // single barrier per t (double buffer covers WAR)
            const float* l1s = l1sh + (t2 & 1) * 48 + 24 * p;
            float u0 = 0.f, u1 = 0.f;
            if (kk == 0) {
                #pragma unroll
                for (int i = 0; i < 24; i += 2) {
                    u0 += l1s[i]     * T0[i];
                    u1 += l1s[i + 1] * T0[i + 1];
                }
            } else if (kk == 1) {
                #pragma unroll
                for (int i = 0; i < 24; i += 2) {
                    u0 += l1s[i]     * T1[i];
                    u1 += l1s[i + 1] * T1[i + 1];
                }
            } else {
                #pragma unroll
                for (int i = 0; i < 24; i += 2) {
                    u0 += l1s[i]     * T2[i];
                    u1 += l1s[i + 1] * T2[i + 1];
                }
            }
            tacc += (u0 + u1) * l2;
            if (p == 0) pacc += yp * l1;

            l1 = l1n; l2 = l2n; yp = ypn; kk = kkn;
        }
        if (c == CH - 1 && p == 0) {   // point-score term for t = T-1
            pacc += ypb[(TT - 1) * NN + j] * ytb[(TT - 1) * NN + j];
        }
        red[tid] = pacc + tacc;
        __syncthreads();
        if (tid == 0) {
            float ssum = 0.f;
            for (int q = 0; q < 96; q++) ssum += red[q];  // fixed order -> deterministic
            g_part[b][c] = ssum;
        }
    }

    // ================= Fused combine: last block to finish does it =================
    __threadfence();                       // publish this block's results
    if (tid == 0) {
        int c = atomicAdd(&g_count, 1);
        s_last = (c == NBLK - 1);
    }
    __syncthreads();
    if (s_last) {
        __threadfence();                   // all other blocks' writes now visible
        if (tid < BB) {
            float q = 0.f;
            #pragma unroll
            for (int c2 = 0; c2 < CH; c2++) q += g_part[tid][c2];  // fixed order
            out[tid] = g_lognorm[tid] - q;
        }
        if (tid == 0) g_count = 0;         // reset for next graph replay
    }
}

extern "C" void kernel_launch(void* const* d_in, const int* in_sizes, int n_in,
                              void* d_out, int out_size)
{
    const float* y_true = (const float*)d_in[0];
    const float* y_pred = (const float*)d_in[1];
    const int*   spkseq = (const int*)d_in[2];
    const float* tr0    = (const float*)d_in[3];
    const float* tr1    = (const float*)d_in[4];
    const float* tr2    = (const float*)d_in[5];

    crf_main<<<NBLK, 96>>>(y_true, y_pred, spkseq, tr0, tr1, tr2, (float*)d_out);
}